// round 17
// baseline (speedup 1.0000x reference)
#include <cuda_runtime.h>
#include <cuda_bf16.h>

// Echo state network, fully fused into ONE kernel.
//   proj = x.reshape(7168,28) @ W_in^T ; h_{t+1} = tanh(proj_t + W_res h_t)
//   h_last[b] = h after step b*28+27 ; out = h_last @ W_out^T + b_out
//
// Scan: thread i's W_res row is ROTATED by 32*warp so its first 32 columns are
// its OWN warp's h values. Those are visible after __syncwarp (own warp wrote
// them), so 8 LDS + 16 FFMA2 execute BEFORE __syncthreads — the barrier drain
// overlaps real work instead of being exposed on the critical path.

#define HIDDEN   128
#define T_STEPS  7168
#define SEQ      28
#define BATCH    256
#define NOUT     10
#define NBLK     112        // T_STEPS / 64

typedef unsigned long long ull;

// +2 zero pad rows (never written) -> unconditional prefetch in the scan
__device__ float g_proj[(T_STEPS + 2) * HIDDEN];
__device__ float g_hlast[BATCH * HIDDEN];
__device__ int   g_sync;

// -------- packed f32x2 helpers (sm_100+) --------
__device__ __forceinline__ ull pack2(float lo, float hi) {
    ull r;
    asm("mov.b64 %0, {%1, %2};" : "=l"(r) : "f"(lo), "f"(hi));
    return r;
}
__device__ __forceinline__ void unpack2(ull v, float& lo, float& hi) {
    asm("mov.b64 {%0, %1}, %2;" : "=f"(lo), "=f"(hi) : "l"(v));
}
__device__ __forceinline__ ull ffma2(ull a, ull b, ull c) {
    ull d;
    asm("fma.rn.f32x2 %0, %1, %2, %3;" : "=l"(d) : "l"(a), "l"(b), "l"(c));
    return d;
}
__device__ __forceinline__ ull fadd2(ull a, ull b) {
    ull d;
    asm("add.rn.f32x2 %0, %1, %2;" : "=l"(d) : "l"(a), "l"(b));
    return d;
}
__device__ __forceinline__ float tanh_mufu(float x) {
    float y;
    asm("tanh.approx.f32 %0, %1;" : "=f"(y) : "f"(x));
    return y;
}

__global__ __launch_bounds__(128, 1) void esn_fused_kernel(
    const float* __restrict__ x,     const float* __restrict__ W_in,
    const float* __restrict__ W_res, const float* __restrict__ W_out,
    const float* __restrict__ b_out, float* __restrict__ out)
{
    __shared__ float sx[64 * SEQ];                    // x tile (proj phase)
    // double-buffered, DUPLICATED h rows (rotated reads span [ROT, ROT+128))
    __shared__ __align__(16) float hbuf[2][256];

    const int i   = threadIdx.x;                      // hidden row 0..127
    const int blk = blockIdx.x;
    const int ROT = i & 96;                           // 32 * warp_id

    // ================= Phase 1: proj slice =================
    {
        const int t0 = blk * 64;
        float wi[SEQ];
        #pragma unroll
        for (int d = 0; d < SEQ; d++) wi[d] = __ldg(&W_in[i * SEQ + d]);

        for (int k = i; k < 64 * SEQ; k += 128) sx[k] = x[t0 * SEQ + k];
        __syncthreads();

        #pragma unroll 4
        for (int tl = 0; tl < 64; tl++) {
            const float* xr = &sx[tl * SEQ];          // broadcast
            float a = 0.f;
            #pragma unroll
            for (int d = 0; d < SEQ; d++) a = fmaf(xr[d], wi[d], a);
            g_proj[(t0 + tl) * HIDDEN + i] = a;       // coalesced
        }
    }

    __threadfence();
    __syncthreads();
    if (i == 0) atomicAdd(&g_sync, 1);
    if (blk != 0) return;

    // ==== Block 0: load W_res row ROTATED by ROT (overlaps the spin) ====
    // w[j] multiplies h[(ROT + 2j) & 127 .. +1]; own-warp block = w[0..15].
    ull w[64];
    {
        const float* wrow = W_res + i * HIDDEN;
        #pragma unroll
        for (int j = 0; j < 64; j++) {
            int col = (ROT + 2 * j) & 127;
            float2 v = *(const float2*)(wrow + col);
            w[j] = pack2(v.x, v.y);
        }
    }

    if (i == 0) {
        while (atomicAdd(&g_sync, 0) < NBLK) { }
        atomicExch(&g_sync, 0);                       // reset for next replay
    }
    __syncthreads();
    __threadfence();

    // ================= Phase 2: serial scan =================
    hbuf[0][i] = 0.f;
    hbuf[0][i + 128] = 0.f;
    __syncthreads();

    float pc = __ldcg(&g_proj[i]);
    float pn = __ldcg(&g_proj[HIDDEN + i]);
    const float* pptr = &g_proj[2 * HIDDEN + i];
    int cnt = 0, batch = 0;

    for (int t = 0; t < T_STEPS; t++) {
        const float* src = hbuf[t & 1];
        float*       dst = hbuf[(t + 1) & 1];
        const ulonglong2* h2 = (const ulonglong2*)(src + ROT);

        // ---- own-warp block: visible after the __syncwarp at loop end ----
        ull a0 = pack2(pc, 0.f), a1 = 0ull, a2 = 0ull, a3 = 0ull;
        {
            ulonglong2 v0 = h2[0], v1 = h2[1], v2 = h2[2], v3 = h2[3];
            ulonglong2 v4 = h2[4], v5 = h2[5], v6 = h2[6], v7 = h2[7];
            a0 = ffma2(w[0], v0.x, a0);  a1 = ffma2(w[1], v0.y, a1);
            a2 = ffma2(w[2], v1.x, a2);  a3 = ffma2(w[3], v1.y, a3);
            a0 = ffma2(w[4], v2.x, a0);  a1 = ffma2(w[5], v2.y, a1);
            a2 = ffma2(w[6], v3.x, a2);  a3 = ffma2(w[7], v3.y, a3);
            a0 = ffma2(w[8], v4.x, a0);  a1 = ffma2(w[9], v4.y, a1);
            a2 = ffma2(w[10], v5.x, a2); a3 = ffma2(w[11], v5.y, a3);
            a0 = ffma2(w[12], v6.x, a0); a1 = ffma2(w[13], v6.y, a1);
            a2 = ffma2(w[14], v7.x, a2); a3 = ffma2(w[15], v7.y, a3);
        }

        float pf = __ldcg(pptr);                      // pad rows -> no guard
        pptr += HIDDEN;

        __syncthreads();                              // other warps' h now visible
                                                      // (drain overlapped above)

        // ---- remaining 96 values: 24 x LDS.128 + 48 x f32x2-FMA ----
        #pragma unroll
        for (int j = 2; j < 8; j++) {
            ulonglong2 v0 = h2[4 * j + 0];
            ulonglong2 v1 = h2[4 * j + 1];
            ulonglong2 v2 = h2[4 * j + 2];
            ulonglong2 v3 = h2[4 * j + 3];
            a0 = ffma2(w[8 * j + 0], v0.x, a0);
            a1 = ffma2(w[8 * j + 1], v0.y, a1);
            a2 = ffma2(w[8 * j + 2], v1.x, a2);
            a3 = ffma2(w[8 * j + 3], v1.y, a3);
            a0 = ffma2(w[8 * j + 4], v2.x, a0);
            a1 = ffma2(w[8 * j + 5], v2.y, a1);
            a2 = ffma2(w[8 * j + 6], v3.x, a2);
            a3 = ffma2(w[8 * j + 7], v3.y, a3);
        }

        // ---- reduce + native MUFU tanh ----
        ull s01 = fadd2(a0, a1);
        ull s23 = fadd2(a2, a3);
        ull st  = fadd2(s01, s23);
        float lo, hi;
        unpack2(st, lo, hi);
        float hn = tanh_mufu(lo + hi);

        dst[i] = hn;                                  // both copies (rotation wrap)
        dst[i + 128] = hn;

        if (++cnt == SEQ) {                           // end of batch: record state
            cnt = 0;
            g_hlast[batch * HIDDEN + i] = hn;
            batch++;
        }

        pc = pn;
        pn = pf;
        __syncwarp();                                 // own-warp h visible next iter
    }

    // ================= Phase 3: output head =================
    __syncthreads();
    for (int e = i; e < BATCH * NOUT; e += 128) {
        int b = e / NOUT;
        int o = e - b * NOUT;
        const float* hr = g_hlast + b * HIDDEN;
        const float* wr = W_out + o * HIDDEN;
        float a = __ldg(&b_out[o]);
        #pragma unroll 8
        for (int h = 0; h < HIDDEN; h++)
            a = fmaf(hr[h], __ldg(&wr[h]), a);
        out[e] = a;
    }
}

extern "C" void kernel_launch(void* const* d_in, const int* in_sizes, int n_in,
                              void* d_out, int out_size)
{
    const float* x     = (const float*)d_in[0];
    const float* W_in  = (const float*)d_in[1];
    const float* W_res = (const float*)d_in[2];
    const float* W_out = (const float*)d_in[3];
    const float* b_out = (const float*)d_in[4];
    float* out = (float*)d_out;

    esn_fused_kernel<<<NBLK, 128>>>(x, W_in, W_res, W_out, b_out, out);
}